// round 14
// baseline (speedup 1.0000x reference)
#include <cuda_runtime.h>
#include <cuda_bf16.h>

#define EPSV 1e-7f
#define MAXN 50000
#define WS 68     // transposed weight row stride (floats), float4-aligned
#define XSTR 68   // x staging row stride (floats); node1 col offset +33

typedef unsigned long long u64;
struct __align__(16) U64x2 { u64 x, y; };

// ------------------------- static device scratch ---------------------------
__device__ __align__(16) float4 g_xt4[MAXN * 16];   // fp32 xtan
__device__ __align__(8) float2 g_ns2[MAXN];         // {||hb||^2, 1/at}
__device__ __align__(16) float g_agg[MAXN * 64];    // fp32 accumulators
// bf16 tables for the edge kernel (4 dims per uint2)
__device__ __align__(16) uint2 g_Ph [MAXN * 16];
__device__ __align__(16) uint2 g_Qh [MAXN * 16];
__device__ __align__(16) uint2 g_xth[MAXN * 16];

// ------------------------------ helpers ------------------------------------
__device__ __forceinline__ float artanh_c(float x) {
    x = fminf(x, 1.0f - EPSV);
    return 0.5f * __logf(__fdividef(1.0f + x, 1.0f - x));
}
__device__ __forceinline__ float tanh_pos(float x) {  // x >= 0
    float e = __expf(-2.0f * x);
    return (1.0f - e) * __fdividef(1.0f, 1.0f + e);
}
__device__ __forceinline__ float sigmoidf_(float z) {
    return __fdividef(1.0f, 1.0f + __expf(-z));
}
__device__ __forceinline__ float siluf_(float z) {   // exact (output path)
    return z * sigmoidf_(z);
}
__device__ __forceinline__ float tanh_fast(float x) {
    float r;
    asm("tanh.approx.f32 %0, %1;" : "=f"(r) : "f"(x));
    return r;
}
__device__ __forceinline__ float silu_fast(float x) {
    float t = tanh_fast(0.5f * x);
    return fmaf(0.5f * x, t, 0.5f * x);
}
__device__ __forceinline__ float sigmoid_fast(float z) {
    return fmaf(0.5f, tanh_fast(0.5f * z), 0.5f);
}
__device__ __forceinline__ void red_add_v4(float* a, float x, float y, float z, float w) {
    asm volatile("red.global.add.v4.f32 [%0], {%1, %2, %3, %4};"
                 :: "l"(a), "f"(x), "f"(y), "f"(z), "f"(w) : "memory");
}
__device__ __forceinline__ unsigned pk2(float a, float b) {
    __nv_bfloat162 t = __floats2bfloat162_rn(a, b);
    return *reinterpret_cast<unsigned*>(&t);
}
__device__ __forceinline__ float2 upk(unsigned u) {
    __nv_bfloat162 t = *reinterpret_cast<__nv_bfloat162*>(&u);
    return __bfloat1622float2(t);
}
__device__ __forceinline__ u64 pk64(float a, float b) {
    u64 r;
    asm("mov.b64 %0, {%1, %2};" : "=l"(r) : "f"(a), "f"(b));
    return r;
}
__device__ __forceinline__ float2 up64(u64 v) {
    float2 r;
    asm("mov.b64 {%0, %1}, %2;" : "=f"(r.x), "=f"(r.y) : "l"(v));
    return r;
}
__device__ __forceinline__ float psum(float v) {     // reduce over (2k,2k+1) pair
    return v + __shfl_xor_sync(0xffffffffu, v, 1);
}

// Dual-node half-output GEMV: thread p computes outputs o=8j+4p+{0..3} for
// nodes in columns col0=slot and col1=slot+33. Weight LDS shared by both.
#define GEMVH2(a0, a1, sxp, swp, slot, p4)                                    \
    do {                                                                      \
        _Pragma("unroll 4")                                                   \
        for (int k = 0; k < 64; ++k) {                                        \
            float xk0 = (sxp)[k * XSTR + (slot)];                             \
            float xk1 = (sxp)[k * XSTR + (slot) + 33];                        \
            u64 x0_2, x1_2;                                                   \
            asm("mov.b64 %0, {%1, %1};" : "=l"(x0_2) : "f"(xk0));             \
            asm("mov.b64 %0, {%1, %1};" : "=l"(x1_2) : "f"(xk1));             \
            const float* wrow = (swp) + k * WS + (p4);                        \
            _Pragma("unroll")                                                 \
            for (int j = 0; j < 8; ++j) {                                     \
                U64x2 w2 = *reinterpret_cast<const U64x2*>(wrow + 8 * j);     \
                asm("fma.rn.f32x2 %0, %1, %2, %0;"                            \
                    : "+l"(a0[2 * j]) : "l"(w2.x), "l"(x0_2));                \
                asm("fma.rn.f32x2 %0, %1, %2, %0;"                            \
                    : "+l"(a0[2 * j + 1]) : "l"(w2.y), "l"(x0_2));            \
                asm("fma.rn.f32x2 %0, %1, %2, %0;"                            \
                    : "+l"(a1[2 * j]) : "l"(w2.x), "l"(x1_2));                \
                asm("fma.rn.f32x2 %0, %1, %2, %0;"                            \
                    : "+l"(a1[2 * j + 1]) : "l"(w2.y), "l"(x1_2));            \
            }                                                                 \
        }                                                                     \
    } while (0)

// hyperbolic chain for one node: consumes acc (xt halves), produces hb in acc,
// stages hb into sx column, writes node tables (ns2, xt4, xth, agg-zero).
__device__ __forceinline__ void hyp_chain(
    u64* acc, const float* sb, int p4, float* sx, int col,
    int nd, bool valid, int p) {
    float xsq = 0.f, bsq = 0.f, rbp = 0.f;
#pragma unroll
    for (int j = 0; j < 8; ++j) {
        float2 v0 = up64(acc[2 * j]);
        float2 v1 = up64(acc[2 * j + 1]);
        const float2* bp = reinterpret_cast<const float2*>(sb + 8 * j + p4);
        float2 b0 = bp[0], b1 = bp[1];
        xsq += v0.x * v0.x + v0.y * v0.y + v1.x * v1.x + v1.y * v1.y;
        bsq += b0.x * b0.x + b0.y * b0.y + b1.x * b1.x + b1.y * b1.y;
        rbp += v0.x * b0.x + v0.y * b0.y + v1.x * b1.x + v1.y * b1.y;
    }
    xsq = psum(xsq); bsq = psum(bsq); rbp = psum(rbp);

    float nx = fmaxf(sqrtf(xsq), EPSV);
    float s0 = tanh_pos(nx) * __fdividef(1.0f, nx);
    float res2 = xsq * s0 * s0;
    float omr = 1.0f - res2;
    float rb = rbp * s0;

    float usq = bsq * omr * omr;
    float nu = fmaxf(sqrtf(usq), EPSV);
    float lam = 2.0f * __fdividef(1.0f, fmaxf(omr, EPSV));
    float ws = tanh_pos(0.5f * lam * nu) * __fdividef(1.0f, nu);
    float y2 = usq * ws * ws;
    float xy = ws * omr * rb;
    float ca = 1.0f + 2.0f * xy + y2;
    float den = fmaxf(1.0f + 2.0f * xy + res2 * y2, EPSV);
    float inv = __fdividef(1.0f, den);
    float c1 = ca * s0 * inv;
    float c2 = omr * omr * ws * inv;

    float hbsq = 0.f;
#pragma unroll
    for (int j = 0; j < 8; ++j) {
        float2 v0 = up64(acc[2 * j]);
        float2 v1 = up64(acc[2 * j + 1]);
        const float2* bp = reinterpret_cast<const float2*>(sb + 8 * j + p4);
        float2 b0 = bp[0], b1 = bp[1];
        float h0 = c1 * v0.x + c2 * b0.x;
        float h1 = c1 * v0.y + c2 * b0.y;
        float h2 = c1 * v1.x + c2 * b1.x;
        float h3 = c1 * v1.y + c2 * b1.y;
        hbsq += h0 * h0 + h1 * h1 + h2 * h2 + h3 * h3;
        acc[2 * j]     = pk64(h0, h1);
        acc[2 * j + 1] = pk64(h2, h3);
        int ob = 8 * j + p4;
        sx[(ob + 0) * XSTR + col] = h0;
        sx[(ob + 1) * XSTR + col] = h1;
        sx[(ob + 2) * XSTR + col] = h2;
        sx[(ob + 3) * XSTR + col] = h3;
    }
    hbsq = psum(hbsq);
    float nbn = fmaxf(sqrtf(hbsq), EPSV);
    float at = artanh_c(nbn) * __fdividef(1.0f, nbn);

    if (valid) {
        if (p == 0) g_ns2[nd] = make_float2(hbsq, __fdividef(1.0f, at));
        uint2*  gth = g_xth + (size_t)nd * 16;
        float4* gxt = g_xt4 + (size_t)nd * 16;
        float4* gag = reinterpret_cast<float4*>(g_agg) + (size_t)nd * 16;
#pragma unroll
        for (int j = 0; j < 8; ++j) {
            int u = 2 * j + p;
            float2 v0 = up64(acc[2 * j]);
            float2 v1 = up64(acc[2 * j + 1]);
            float4 xt = make_float4(v0.x * at, v0.y * at, v1.x * at, v1.y * at);
            gxt[u] = xt;
            gth[u] = make_uint2(pk2(xt.x, xt.y), pk2(xt.z, xt.w));
            gag[u] = make_float4(0.f, 0.f, 0.f, 0.f);
        }
    }
}

// ======= K1 (2 thr/node, 2 nodes/thread, 64 nodes/block of 64 thr) ==========
__global__ void __launch_bounds__(64)
k_nodeA(const float* __restrict__ h,
        const float* __restrict__ Wlin,
        const float* __restrict__ blin,
        const float* __restrict__ Wa1,
        const float* __restrict__ ba1, int n) {
    __shared__ float sW[64 * WS];
    __shared__ float sx[64 * XSTR];
    __shared__ __align__(16) float sb[64];

    const int tid = threadIdx.x;
    const int slot = tid >> 1, p = tid & 1, p4 = 4 * p;
    const int base = blockIdx.x * 64;
    const int n0 = base + slot, n1 = base + slot + 32;
    const bool v0 = n0 < n, v1 = n1 < n;
    const int d0 = v0 ? n0 : 0, d1 = v1 ? n1 : 0;

    // stage Wlin^T + blin
    for (int idx = tid; idx < 4096; idx += 64) {
        int o = idx >> 6, k = idx & 63;
        sW[k * WS + o] = Wlin[idx];
    }
    sb[tid] = blin[tid];
    __syncthreads();

    // stage lm for both nodes
#pragma unroll
    for (int m = 0; m < 2; ++m) {
        int nd = m ? d1 : d0;
        int col = slot + m * 33;
        const float4* hp = reinterpret_cast<const float4*>(h) + (size_t)nd * 16 + p * 8;
        float4 hv[8];
        float hsq = 0.f;
#pragma unroll
        for (int i = 0; i < 8; ++i) {
            hv[i] = hp[i];
            hsq += hv[i].x * hv[i].x + hv[i].y * hv[i].y + hv[i].z * hv[i].z + hv[i].w * hv[i].w;
        }
        hsq = psum(hsq);
        float nh = fmaxf(sqrtf(hsq), EPSV);
        float a = artanh_c(nh) * __fdividef(1.0f, nh);
#pragma unroll
        for (int i = 0; i < 8; ++i) {
            int kb = 32 * p + 4 * i;
            sx[(kb + 0) * XSTR + col] = hv[i].x * a;
            sx[(kb + 1) * XSTR + col] = hv[i].y * a;
            sx[(kb + 2) * XSTR + col] = hv[i].z * a;
            sx[(kb + 3) * XSTR + col] = hv[i].w * a;
        }
    }
    __syncwarp();

    // GEMV1 (dual): xt for both nodes
    u64 acc0[16], acc1[16];
#pragma unroll
    for (int j = 0; j < 16; ++j) { acc0[j] = 0ull; acc1[j] = 0ull; }
    GEMVH2(acc0, acc1, sx, sW, slot, p4);

    // hyperbolic chain + table writes + hb restage (per node)
    hyp_chain(acc0, sb, p4, sx, slot,      d0, v0, p);
    hyp_chain(acc1, sb, p4, sx, slot + 33, d1, v1, p);

    // restage Wa1[:,0:64]^T + ba1 ; GEMV P (dual)
    __syncthreads();
    for (int idx = tid; idx < 4096; idx += 64) {
        int o = idx >> 6, k = idx & 63;
        sW[k * WS + o] = Wa1[o * 130 + k];
    }
    sb[tid] = ba1[tid];
    __syncthreads();

#pragma unroll
    for (int j = 0; j < 16; ++j) { acc0[j] = 0ull; acc1[j] = 0ull; }
    GEMVH2(acc0, acc1, sx, sW, slot, p4);
#pragma unroll
    for (int m = 0; m < 2; ++m) {
        bool vm = m ? v1 : v0;
        if (!vm) continue;
        int nd = m ? d1 : d0;
        u64* am = m ? acc1 : acc0;
        uint2* gp = g_Ph + (size_t)nd * 16;
#pragma unroll
        for (int j = 0; j < 8; ++j) {
            float2 w0 = up64(am[2 * j]);
            float2 w1 = up64(am[2 * j + 1]);
            const float2* bp = reinterpret_cast<const float2*>(sb + 8 * j + p4);
            float2 b0 = bp[0], b1 = bp[1];
            gp[2 * j + p] = make_uint2(pk2(w0.x + b0.x, w0.y + b0.y),
                                       pk2(w1.x + b1.x, w1.y + b1.y));
        }
    }

    // restage Wa1[:,64:128]^T ; GEMV Q (dual)
    __syncthreads();
    for (int idx = tid; idx < 4096; idx += 64) {
        int o = idx >> 6, k = idx & 63;
        sW[k * WS + o] = Wa1[o * 130 + 64 + k];
    }
    __syncthreads();

#pragma unroll
    for (int j = 0; j < 16; ++j) { acc0[j] = 0ull; acc1[j] = 0ull; }
    GEMVH2(acc0, acc1, sx, sW, slot, p4);
#pragma unroll
    for (int m = 0; m < 2; ++m) {
        bool vm = m ? v1 : v0;
        if (!vm) continue;
        int nd = m ? d1 : d0;
        u64* am = m ? acc1 : acc0;
        uint2* gq = g_Qh + (size_t)nd * 16;
#pragma unroll
        for (int j = 0; j < 8; ++j) {
            float2 w0 = up64(am[2 * j]);
            float2 w1 = up64(am[2 * j + 1]);
            gq[2 * j + p] = make_uint2(pk2(w0.x, w0.y), pk2(w1.x, w1.y));
        }
    }
}

// ===== K2: edge attention + scatter (8 lanes/edge; xt-based dot, no hb) =====
__global__ void __launch_bounds__(256)
k_edge(const int* __restrict__ edges,
       const float* __restrict__ dist,
       const float* __restrict__ emask,
       const float* __restrict__ Wa1,
       const float* __restrict__ Wa2,
       const float* __restrict__ ba2, int E) {
    __shared__ int   s_r [8][32];
    __shared__ int   s_c [8][32];
    __shared__ float s_xy[8][32];
    __shared__ float s_dh[8][32];
    __shared__ float s_dd[8][32];
    __shared__ float s_em[8][32];

    const int lane = threadIdx.x & 31, w = threadIdx.x >> 5;
    const int g = lane >> 3, l8 = lane & 7;       // 4 edge-groups of 8 lanes
    const unsigned FM = 0xffffffffu;

    // per-lane weights for hidden dims [8*l8, 8*l8+8)
    float wdv[8], wddv[8], wa2v[8];
#pragma unroll
    for (int u = 0; u < 8; ++u) {
        wdv[u]  = Wa1[(8 * l8 + u) * 130 + 128];
        wddv[u] = Wa1[(8 * l8 + u) * 130 + 129];
        wa2v[u] = Wa2[8 * l8 + u];
    }
    float b2s = ba2[0];

    const int chunks = (E + 31) >> 5;
    const int ch = blockIdx.x * 8 + w;            // exact-fit: one chunk per warp
    if (ch >= chunks) return;

    int e = ch * 32 + lane;
    bool v = e < E;
    int r = 0, c = 0;
    float dd = 0.f, em = 0.f;
    float sr = 0.f, sc_ = 0.f, scale = 0.f;
    if (v) {
        r = edges[e];
        c = edges[E + e];
        dd = dist[e];
        em = emask[e];
        float2 nr = g_ns2[r];
        float2 nc = g_ns2[c];
        sr = nr.x; sc_ = nc.x;
        scale = nr.y * nc.y;                      // inva_r * inva_c
    }
    s_r[w][lane] = r; s_c[w][lane] = c;
    s_dd[w][lane] = dd; s_em[w][lane] = em;
    __syncwarp();

    const uint4* P4p = reinterpret_cast<const uint4*>(g_Ph);
    const uint4* Q4p = reinterpret_cast<const uint4*>(g_Qh);
    const uint4* X4p = reinterpret_cast<const uint4*>(g_xth);

    // ---- phase 1: per-edge dot of xt (retain xt_c regs for scatter) ----
    uint4 xc[8];
#pragma unroll
    for (int i = 0; i < 8; ++i) {
        int ei = 4 * i + g;
        int er = s_r[w][ei], ec = s_c[w][ei];
        uint4 xr = X4p[er * 8 + l8];
        xc[i] = X4p[ec * 8 + l8];
        float2 a0 = upk(xr.x), a1 = upk(xr.y), a2 = upk(xr.z), a3 = upk(xr.w);
        float2 b0 = upk(xc[i].x), b1 = upk(xc[i].y), b2 = upk(xc[i].z), b3 = upk(xc[i].w);
        float d = a0.x * b0.x + a0.y * b0.y + a1.x * b1.x + a1.y * b1.y
                + a2.x * b2.x + a2.y * b2.y + a3.x * b3.x + a3.y * b3.y;
        d += __shfl_xor_sync(FM, d, 4);
        d += __shfl_xor_sync(FM, d, 2);
        d += __shfl_xor_sync(FM, d, 1);
        if (l8 == 0) s_xy[w][ei] = d;
    }
    __syncwarp();

    // ---- phase 2: hyperbolic distance (lane = edge) ----
    {
        float xyv = s_xy[w][lane] * scale;        // hb dot from xt dot
        float al = 1.0f - 2.0f * xyv + sc_;
        float be = 1.0f - sr;
        float num2 = al * al * sr + be * be * sc_ - 2.0f * al * be * xyv;
        float den = fmaxf(1.0f - 2.0f * xyv + sr * sc_, EPSV);
        float nrm = __fdividef(sqrtf(fmaxf(num2, 0.0f)), den);
        s_dh[w][lane] = 2.0f * artanh_c(nrm);
    }
    __syncwarp();

    // ---- fused phases 3-5: hidden + z + score + scatter (retained xt_c) ----
#pragma unroll
    for (int i = 0; i < 8; ++i) {
        int ei = 4 * i + g;
        int er = s_r[w][ei];
        float dh = s_dh[w][ei], di = s_dd[w][ei];
        float emi = s_em[w][ei];
        uint4 pu = P4p[er * 8 + l8];
        uint4 qu = Q4p[s_c[w][ei] * 8 + l8];
        float2 p0 = upk(pu.x), p1 = upk(pu.y), p2 = upk(pu.z), p3 = upk(pu.w);
        float2 q0 = upk(qu.x), q1 = upk(qu.y), q2 = upk(qu.z), q3 = upk(qu.w);
        float hv[8];
        hv[0] = p0.x + q0.x; hv[1] = p0.y + q0.y;
        hv[2] = p1.x + q1.x; hv[3] = p1.y + q1.y;
        hv[4] = p2.x + q2.x; hv[5] = p2.y + q2.y;
        hv[6] = p3.x + q3.x; hv[7] = p3.y + q3.y;
        float z = 0.f;
#pragma unroll
        for (int u = 0; u < 8; ++u) {
            float t = fmaf(di, wddv[u], fmaf(dh, wdv[u], hv[u]));
            z = fmaf(silu_fast(t), wa2v[u], z);
        }
        z += __shfl_xor_sync(FM, z, 4);
        z += __shfl_xor_sync(FM, z, 2);
        z += __shfl_xor_sync(FM, z, 1);
        float score = sigmoid_fast(z + b2s) * emi;   // em=0 on tail
        float2 x0 = upk(xc[i].x), x1 = upk(xc[i].y);
        float2 x2 = upk(xc[i].z), x3 = upk(xc[i].w);
        float* dst = &g_agg[er * 64 + l8 * 8];
        red_add_v4(dst,     x0.x * score, x0.y * score, x1.x * score, x1.y * score);
        red_add_v4(dst + 4, x2.x * score, x2.y * score, x3.x * score, x3.y * score);
    }
}

// ===== K3 (2 thr/node, 2 nodes/thread): MLP + epilogue ======================
__global__ void __launch_bounds__(64)
k_node3(const float* __restrict__ Wm1,
        const float* __restrict__ bm1,
        const float* __restrict__ Wm2,
        const float* __restrict__ bm2,
        float* __restrict__ out, int n) {
    __shared__ float sW[64 * WS];
    __shared__ float sx[64 * XSTR];
    __shared__ __align__(16) float sb1[64];
    __shared__ __align__(16) float sb2[64];

    const int tid = threadIdx.x;
    const int slot = tid >> 1, p = tid & 1, p4 = 4 * p;
    const int base = blockIdx.x * 64;
    const int n0 = base + slot, n1 = base + slot + 32;
    const bool v0 = n0 < n, v1 = n1 < n;
    const int d0 = v0 ? n0 : 0, d1 = v1 ? n1 : 0;

    for (int idx = tid; idx < 4096; idx += 64) {
        int o = idx >> 6, k = idx & 63;
        sW[k * WS + o] = Wm1[idx];
    }
    sb1[tid] = bm1[tid];
    sb2[tid] = bm2[tid];
    __syncthreads();

    // stage agg/100 for both nodes
#pragma unroll
    for (int m = 0; m < 2; ++m) {
        int nd = m ? d1 : d0;
        int col = slot + m * 33;
        const float4* gag = reinterpret_cast<const float4*>(g_agg) + (size_t)nd * 16 + p * 8;
#pragma unroll
        for (int i = 0; i < 8; ++i) {
            float4 vv = gag[i];
            int kb = 32 * p + 4 * i;
            sx[(kb + 0) * XSTR + col] = vv.x * 0.01f;
            sx[(kb + 1) * XSTR + col] = vv.y * 0.01f;
            sx[(kb + 2) * XSTR + col] = vv.z * 0.01f;
            sx[(kb + 3) * XSTR + col] = vv.w * 0.01f;
        }
    }
    __syncwarp();

    // GEMV1 (dual)
    u64 acc0[16], acc1[16];
#pragma unroll
    for (int j = 0; j < 16; ++j) { acc0[j] = 0ull; acc1[j] = 0ull; }
    GEMVH2(acc0, acc1, sx, sW, slot, p4);

    // hid = silu_fast(acc + b1) staged back (interleaved outputs)
#pragma unroll
    for (int m = 0; m < 2; ++m) {
        int col = slot + m * 33;
        u64* am = m ? acc1 : acc0;
#pragma unroll
        for (int j = 0; j < 8; ++j) {
            float2 w0 = up64(am[2 * j]);
            float2 w1 = up64(am[2 * j + 1]);
            const float2* bp = reinterpret_cast<const float2*>(sb1 + 8 * j + p4);
            float2 b0 = bp[0], b1 = bp[1];
            int ob = 8 * j + p4;
            sx[(ob + 0) * XSTR + col] = silu_fast(w0.x + b0.x);
            sx[(ob + 1) * XSTR + col] = silu_fast(w0.y + b0.y);
            sx[(ob + 2) * XSTR + col] = silu_fast(w1.x + b1.x);
            sx[(ob + 3) * XSTR + col] = silu_fast(w1.y + b1.y);
        }
    }

    // restage Wm2
    __syncthreads();
    for (int idx = tid; idx < 4096; idx += 64) {
        int o = idx >> 6, k = idx & 63;
        sW[k * WS + o] = Wm2[idx];
    }
    __syncthreads();

    // GEMV2 (dual)
#pragma unroll
    for (int j = 0; j < 16; ++j) { acc0[j] = 0ull; acc1[j] = 0ull; }
    GEMVH2(acc0, acc1, sx, sW, slot, p4);

    // epilogue per node
#pragma unroll
    for (int m = 0; m < 2; ++m) {
        bool vm = m ? v1 : v0;
        int nd = m ? d1 : d0;
        u64* am = m ? acc1 : acc0;

        const float4* gxt = g_xt4 + (size_t)nd * 16;
        float ysq = 0.f;
#pragma unroll
        for (int j = 0; j < 8; ++j) {
            float4 xt = gxt[2 * j + p];
            float2 w0 = up64(am[2 * j]);
            float2 w1 = up64(am[2 * j + 1]);
            const float2* bp = reinterpret_cast<const float2*>(sb2 + 8 * j + p4);
            float2 b0 = bp[0], b1 = bp[1];
            float y0 = w0.x + b0.x + xt.x;
            float y1 = w0.y + b0.y + xt.y;
            float y2 = w1.x + b1.x + xt.z;
            float y3 = w1.y + b1.y + xt.w;
            ysq += y0 * y0 + y1 * y1 + y2 * y2 + y3 * y3;
            am[2 * j]     = pk64(y0, y1);
            am[2 * j + 1] = pk64(y2, y3);
        }
        ysq = psum(ysq);

        float ny = fmaxf(sqrtf(ysq), EPSV);
        float t = tanh_pos(ny);
        float s1 = t * __fdividef(1.0f, ny);
        float no = fmaxf(t, EPSV);                    // ||expmap0(y)|| = tanh(ny)
        float a2 = artanh_c(no) * __fdividef(1.0f, no);
        float sc = s1 * a2;

        float ssq = 0.f;
#pragma unroll
        for (int j = 0; j < 16; ++j) {
            float2 vv = up64(am[j]);
            float sx0 = siluf_(vv.x * sc);
            float sx1 = siluf_(vv.y * sc);
            ssq += sx0 * sx0 + sx1 * sx1;
            am[j] = pk64(sx0, sx1);
        }
        ssq = psum(ssq);
        float ns = fmaxf(sqrtf(ssq), EPSV);
        float s3 = tanh_pos(ns) * __fdividef(1.0f, ns);

        if (vm) {
            float4* op = reinterpret_cast<float4*>(out) + (size_t)nd * 16;
#pragma unroll
            for (int j = 0; j < 8; ++j) {
                float2 w0 = up64(am[2 * j]);
                float2 w1 = up64(am[2 * j + 1]);
                op[2 * j + p] = make_float4(w0.x * s3, w0.y * s3, w1.x * s3, w1.y * s3);
            }
        }
    }
}

// ------------------------------- launch -------------------------------------
extern "C" void kernel_launch(void* const* d_in, const int* in_sizes, int n_in,
                              void* d_out, int out_size) {
    const float* h         = (const float*)d_in[0];
    const float* distances = (const float*)d_in[1];
    const int*   edges     = (const int*)  d_in[2];
    // d_in[3] = node_mask (unused by reference)
    const float* edge_mask = (const float*)d_in[4];
    const float* W_lin     = (const float*)d_in[5];
    const float* b_lin     = (const float*)d_in[6];
    const float* Wa1       = (const float*)d_in[7];
    const float* ba1       = (const float*)d_in[8];
    const float* Wa2       = (const float*)d_in[9];
    const float* ba2       = (const float*)d_in[10];
    const float* Wm1       = (const float*)d_in[11];
    const float* bm1       = (const float*)d_in[12];
    const float* Wm2       = (const float*)d_in[13];
    const float* bm2       = (const float*)d_in[14];

    int N = in_sizes[0] / 64;
    int E = in_sizes[1];

    int blocksN = (N + 63) / 64;               // 64 nodes / 64-thread block
    int chunks = (E + 31) / 32;
    int blocksE = (chunks + 7) / 8;            // exact-fit: 1 chunk per warp

    k_nodeA<<<blocksN, 64>>>(h, W_lin, b_lin, Wa1, ba1, N);
    k_edge <<<blocksE, 256>>>(edges, distances, edge_mask, Wa1, Wa2, ba2, E);
    k_node3<<<blocksN, 64>>>(Wm1, bm1, Wm2, bm2, (float*)d_out, N);
}

// round 15
// speedup vs baseline: 1.0418x; 1.0418x over previous
#include <cuda_runtime.h>
#include <cuda_bf16.h>

#define EPSV 1e-7f
#define MAXN 50000
#define WS 68     // transposed weight row stride (floats), float4-aligned
#define XSTR 68   // x staging row stride (floats); node1 col offset +33

typedef unsigned long long u64;
struct __align__(16) U64x2 { u64 x, y; };

// ------------------------- static device scratch ---------------------------
__device__ __align__(16) float4 g_xt4[MAXN * 16];   // fp32 xtan
__device__ float g_nsq[MAXN];
__device__ __align__(16) float g_agg[MAXN * 64];    // fp32 accumulators
// bf16 tables for the edge kernel (4 dims per uint2)
__device__ __align__(16) uint2 g_hbh[MAXN * 16];
__device__ __align__(16) uint2 g_Ph [MAXN * 16];
__device__ __align__(16) uint2 g_Qh [MAXN * 16];
__device__ __align__(16) uint2 g_xth[MAXN * 16];

// ------------------------------ helpers ------------------------------------
__device__ __forceinline__ float artanh_c(float x) {
    x = fminf(x, 1.0f - EPSV);
    return 0.5f * __logf(__fdividef(1.0f + x, 1.0f - x));
}
__device__ __forceinline__ float tanh_pos(float x) {  // x >= 0
    float e = __expf(-2.0f * x);
    return (1.0f - e) * __fdividef(1.0f, 1.0f + e);
}
__device__ __forceinline__ float sigmoidf_(float z) {
    return __fdividef(1.0f, 1.0f + __expf(-z));
}
__device__ __forceinline__ float siluf_(float z) {   // exact (output path)
    return z * sigmoidf_(z);
}
__device__ __forceinline__ float tanh_fast(float x) {
    float r;
    asm("tanh.approx.f32 %0, %1;" : "=f"(r) : "f"(x));
    return r;
}
__device__ __forceinline__ float silu_fast(float x) {
    float t = tanh_fast(0.5f * x);
    return fmaf(0.5f * x, t, 0.5f * x);
}
__device__ __forceinline__ float sigmoid_fast(float z) {
    return fmaf(0.5f, tanh_fast(0.5f * z), 0.5f);
}
__device__ __forceinline__ void red_add_v4(float* a, float x, float y, float z, float w) {
    asm volatile("red.global.add.v4.f32 [%0], {%1, %2, %3, %4};"
                 :: "l"(a), "f"(x), "f"(y), "f"(z), "f"(w) : "memory");
}
__device__ __forceinline__ unsigned pk2(float a, float b) {
    __nv_bfloat162 t = __floats2bfloat162_rn(a, b);
    return *reinterpret_cast<unsigned*>(&t);
}
__device__ __forceinline__ float2 upk(unsigned u) {
    __nv_bfloat162 t = *reinterpret_cast<__nv_bfloat162*>(&u);
    return __bfloat1622float2(t);
}
__device__ __forceinline__ u64 pk64(float a, float b) {
    u64 r;
    asm("mov.b64 %0, {%1, %2};" : "=l"(r) : "f"(a), "f"(b));
    return r;
}
__device__ __forceinline__ float2 up64(u64 v) {
    float2 r;
    asm("mov.b64 {%0, %1}, %2;" : "=f"(r.x), "=f"(r.y) : "l"(v));
    return r;
}
__device__ __forceinline__ float psum(float v) {     // reduce over (2k,2k+1) pair
    return v + __shfl_xor_sync(0xffffffffu, v, 1);
}

// Dual-node half-output GEMV: thread p computes outputs o=8j+4p+{0..3} for
// nodes in columns col0=slot and col1=slot+33. Weight LDS shared by both.
#define GEMVH2(a0, a1, sxp, swp, slot, p4)                                    \
    do {                                                                      \
        _Pragma("unroll 4")                                                   \
        for (int k = 0; k < 64; ++k) {                                        \
            float xk0 = (sxp)[k * XSTR + (slot)];                             \
            float xk1 = (sxp)[k * XSTR + (slot) + 33];                        \
            u64 x0_2, x1_2;                                                   \
            asm("mov.b64 %0, {%1, %1};" : "=l"(x0_2) : "f"(xk0));             \
            asm("mov.b64 %0, {%1, %1};" : "=l"(x1_2) : "f"(xk1));             \
            const float* wrow = (swp) + k * WS + (p4);                        \
            _Pragma("unroll")                                                 \
            for (int j = 0; j < 8; ++j) {                                     \
                U64x2 w2 = *reinterpret_cast<const U64x2*>(wrow + 8 * j);     \
                asm("fma.rn.f32x2 %0, %1, %2, %0;"                            \
                    : "+l"(a0[2 * j]) : "l"(w2.x), "l"(x0_2));                \
                asm("fma.rn.f32x2 %0, %1, %2, %0;"                            \
                    : "+l"(a0[2 * j + 1]) : "l"(w2.y), "l"(x0_2));            \
                asm("fma.rn.f32x2 %0, %1, %2, %0;"                            \
                    : "+l"(a1[2 * j]) : "l"(w2.x), "l"(x1_2));                \
                asm("fma.rn.f32x2 %0, %1, %2, %0;"                            \
                    : "+l"(a1[2 * j + 1]) : "l"(w2.y), "l"(x1_2));            \
            }                                                                 \
        }                                                                     \
    } while (0)

// hyperbolic chain for one node: consumes acc (xt halves), produces hb in acc,
// stages hb into sx column, writes node tables.
__device__ __forceinline__ void hyp_chain(
    u64* acc, const float* sb, int p4, float* sx, int col,
    int nd, bool valid, int p) {
    float xsq = 0.f, bsq = 0.f, rbp = 0.f;
#pragma unroll
    for (int j = 0; j < 8; ++j) {
        float2 v0 = up64(acc[2 * j]);
        float2 v1 = up64(acc[2 * j + 1]);
        const float2* bp = reinterpret_cast<const float2*>(sb + 8 * j + p4);
        float2 b0 = bp[0], b1 = bp[1];
        xsq += v0.x * v0.x + v0.y * v0.y + v1.x * v1.x + v1.y * v1.y;
        bsq += b0.x * b0.x + b0.y * b0.y + b1.x * b1.x + b1.y * b1.y;
        rbp += v0.x * b0.x + v0.y * b0.y + v1.x * b1.x + v1.y * b1.y;
    }
    xsq = psum(xsq); bsq = psum(bsq); rbp = psum(rbp);

    float nx = fmaxf(sqrtf(xsq), EPSV);
    float s0 = tanh_pos(nx) * __fdividef(1.0f, nx);
    float res2 = xsq * s0 * s0;
    float omr = 1.0f - res2;
    float rb = rbp * s0;

    float usq = bsq * omr * omr;
    float nu = fmaxf(sqrtf(usq), EPSV);
    float lam = 2.0f * __fdividef(1.0f, fmaxf(omr, EPSV));
    float ws = tanh_pos(0.5f * lam * nu) * __fdividef(1.0f, nu);
    float y2 = usq * ws * ws;
    float xy = ws * omr * rb;
    float ca = 1.0f + 2.0f * xy + y2;
    float den = fmaxf(1.0f + 2.0f * xy + res2 * y2, EPSV);
    float inv = __fdividef(1.0f, den);
    float c1 = ca * s0 * inv;
    float c2 = omr * omr * ws * inv;

    float hbsq = 0.f;
#pragma unroll
    for (int j = 0; j < 8; ++j) {
        float2 v0 = up64(acc[2 * j]);
        float2 v1 = up64(acc[2 * j + 1]);
        const float2* bp = reinterpret_cast<const float2*>(sb + 8 * j + p4);
        float2 b0 = bp[0], b1 = bp[1];
        float h0 = c1 * v0.x + c2 * b0.x;
        float h1 = c1 * v0.y + c2 * b0.y;
        float h2 = c1 * v1.x + c2 * b1.x;
        float h3 = c1 * v1.y + c2 * b1.y;
        hbsq += h0 * h0 + h1 * h1 + h2 * h2 + h3 * h3;
        acc[2 * j]     = pk64(h0, h1);
        acc[2 * j + 1] = pk64(h2, h3);
        int ob = 8 * j + p4;
        sx[(ob + 0) * XSTR + col] = h0;
        sx[(ob + 1) * XSTR + col] = h1;
        sx[(ob + 2) * XSTR + col] = h2;
        sx[(ob + 3) * XSTR + col] = h3;
    }
    hbsq = psum(hbsq);
    float nbn = fmaxf(sqrtf(hbsq), EPSV);
    float at = artanh_c(nbn) * __fdividef(1.0f, nbn);

    if (valid) {
        if (p == 0) g_nsq[nd] = hbsq;
        uint2*  gbh = g_hbh + (size_t)nd * 16;
        uint2*  gth = g_xth + (size_t)nd * 16;
        float4* gxt = g_xt4 + (size_t)nd * 16;
        float4* gag = reinterpret_cast<float4*>(g_agg) + (size_t)nd * 16;
#pragma unroll
        for (int j = 0; j < 8; ++j) {
            int u = 2 * j + p;
            float2 v0 = up64(acc[2 * j]);
            float2 v1 = up64(acc[2 * j + 1]);
            gbh[u] = make_uint2(pk2(v0.x, v0.y), pk2(v1.x, v1.y));
            float4 xt = make_float4(v0.x * at, v0.y * at, v1.x * at, v1.y * at);
            gxt[u] = xt;
            gth[u] = make_uint2(pk2(xt.x, xt.y), pk2(xt.z, xt.w));
            gag[u] = make_float4(0.f, 0.f, 0.f, 0.f);
        }
    }
}

// ======= K1 (2 thr/node, 2 nodes/thread, 64 nodes/block of 64 thr) ==========
__global__ void __launch_bounds__(64)
k_nodeA(const float* __restrict__ h,
        const float* __restrict__ Wlin,
        const float* __restrict__ blin,
        const float* __restrict__ Wa1,
        const float* __restrict__ ba1, int n) {
    __shared__ float sW[64 * WS];
    __shared__ float sx[64 * XSTR];
    __shared__ __align__(16) float sb[64];

    const int tid = threadIdx.x;
    const int slot = tid >> 1, p = tid & 1, p4 = 4 * p;
    const int base = blockIdx.x * 64;
    const int n0 = base + slot, n1 = base + slot + 32;
    const bool v0 = n0 < n, v1 = n1 < n;
    const int d0 = v0 ? n0 : 0, d1 = v1 ? n1 : 0;

    // stage Wlin^T + blin
    for (int idx = tid; idx < 4096; idx += 64) {
        int o = idx >> 6, k = idx & 63;
        sW[k * WS + o] = Wlin[idx];
    }
    sb[tid] = blin[tid];
    __syncthreads();

    // stage lm for both nodes
#pragma unroll
    for (int m = 0; m < 2; ++m) {
        int nd = m ? d1 : d0;
        int col = slot + m * 33;
        const float4* hp = reinterpret_cast<const float4*>(h) + (size_t)nd * 16 + p * 8;
        float4 hv[8];
        float hsq = 0.f;
#pragma unroll
        for (int i = 0; i < 8; ++i) {
            hv[i] = hp[i];
            hsq += hv[i].x * hv[i].x + hv[i].y * hv[i].y + hv[i].z * hv[i].z + hv[i].w * hv[i].w;
        }
        hsq = psum(hsq);
        float nh = fmaxf(sqrtf(hsq), EPSV);
        float a = artanh_c(nh) * __fdividef(1.0f, nh);
#pragma unroll
        for (int i = 0; i < 8; ++i) {
            int kb = 32 * p + 4 * i;
            sx[(kb + 0) * XSTR + col] = hv[i].x * a;
            sx[(kb + 1) * XSTR + col] = hv[i].y * a;
            sx[(kb + 2) * XSTR + col] = hv[i].z * a;
            sx[(kb + 3) * XSTR + col] = hv[i].w * a;
        }
    }
    __syncwarp();

    // GEMV1 (dual): xt for both nodes
    u64 acc0[16], acc1[16];
#pragma unroll
    for (int j = 0; j < 16; ++j) { acc0[j] = 0ull; acc1[j] = 0ull; }
    GEMVH2(acc0, acc1, sx, sW, slot, p4);

    // hyperbolic chain + table writes + hb restage (per node)
    hyp_chain(acc0, sb, p4, sx, slot,      d0, v0, p);
    hyp_chain(acc1, sb, p4, sx, slot + 33, d1, v1, p);

    // restage Wa1[:,0:64]^T + ba1 ; GEMV P (dual)
    __syncthreads();
    for (int idx = tid; idx < 4096; idx += 64) {
        int o = idx >> 6, k = idx & 63;
        sW[k * WS + o] = Wa1[o * 130 + k];
    }
    sb[tid] = ba1[tid];
    __syncthreads();

#pragma unroll
    for (int j = 0; j < 16; ++j) { acc0[j] = 0ull; acc1[j] = 0ull; }
    GEMVH2(acc0, acc1, sx, sW, slot, p4);
#pragma unroll
    for (int m = 0; m < 2; ++m) {
        bool vm = m ? v1 : v0;
        if (!vm) continue;
        int nd = m ? d1 : d0;
        u64* am = m ? acc1 : acc0;
        uint2* gp = g_Ph + (size_t)nd * 16;
#pragma unroll
        for (int j = 0; j < 8; ++j) {
            float2 w0 = up64(am[2 * j]);
            float2 w1 = up64(am[2 * j + 1]);
            const float2* bp = reinterpret_cast<const float2*>(sb + 8 * j + p4);
            float2 b0 = bp[0], b1 = bp[1];
            gp[2 * j + p] = make_uint2(pk2(w0.x + b0.x, w0.y + b0.y),
                                       pk2(w1.x + b1.x, w1.y + b1.y));
        }
    }

    // restage Wa1[:,64:128]^T ; GEMV Q (dual)
    __syncthreads();
    for (int idx = tid; idx < 4096; idx += 64) {
        int o = idx >> 6, k = idx & 63;
        sW[k * WS + o] = Wa1[o * 130 + 64 + k];
    }
    __syncthreads();

#pragma unroll
    for (int j = 0; j < 16; ++j) { acc0[j] = 0ull; acc1[j] = 0ull; }
    GEMVH2(acc0, acc1, sx, sW, slot, p4);
#pragma unroll
    for (int m = 0; m < 2; ++m) {
        bool vm = m ? v1 : v0;
        if (!vm) continue;
        int nd = m ? d1 : d0;
        u64* am = m ? acc1 : acc0;
        uint2* gq = g_Qh + (size_t)nd * 16;
#pragma unroll
        for (int j = 0; j < 8; ++j) {
            float2 w0 = up64(am[2 * j]);
            float2 w1 = up64(am[2 * j + 1]);
            gq[2 * j + p] = make_uint2(pk2(w0.x, w0.y), pk2(w1.x, w1.y));
        }
    }
}

// ===== K2: edge attention + scatter (8 lanes/edge, 16-edge chunks) ==========
__global__ void __launch_bounds__(256)
k_edge(const int* __restrict__ edges,
       const float* __restrict__ dist,
       const float* __restrict__ emask,
       const float* __restrict__ Wa1,
       const float* __restrict__ Wa2,
       const float* __restrict__ ba2, int E) {
    __shared__ int   s_r [8][16];
    __shared__ int   s_c [8][16];
    __shared__ float s_xy[8][16];
    __shared__ float s_dh[8][16];
    __shared__ float s_dd[8][16];
    __shared__ float s_em[8][16];

    const int lane = threadIdx.x & 31, w = threadIdx.x >> 5;
    const int g = lane >> 3, l8 = lane & 7;       // 4 edge-groups of 8 lanes
    const unsigned FM = 0xffffffffu;

    // per-lane weights for hidden dims [8*l8, 8*l8+8)
    float wdv[8], wddv[8], wa2v[8];
#pragma unroll
    for (int u = 0; u < 8; ++u) {
        wdv[u]  = Wa1[(8 * l8 + u) * 130 + 128];
        wddv[u] = Wa1[(8 * l8 + u) * 130 + 129];
        wa2v[u] = Wa2[8 * l8 + u];
    }
    float b2s = ba2[0];

    const int chunks = (E + 15) >> 4;             // 16 edges per warp
    const int ch = blockIdx.x * 8 + w;
    if (ch >= chunks) return;

    int e = ch * 16 + lane;
    bool v = (lane < 16) && (e < E);
    int r = 0, c = 0;
    float dd = 0.f, em = 0.f, sr = 0.f, sc_ = 0.f;
    if (v) {
        r = edges[e];
        c = edges[E + e];
        dd = dist[e];
        em = emask[e];
        sr = g_nsq[r];
        sc_ = g_nsq[c];
    }
    if (lane < 16) {
        s_r[w][lane] = r; s_c[w][lane] = c;
        s_dd[w][lane] = dd; s_em[w][lane] = em;
    }
    __syncwarp();

    const uint4* hb4 = reinterpret_cast<const uint4*>(g_hbh);
    const uint4* P4p = reinterpret_cast<const uint4*>(g_Ph);
    const uint4* Q4p = reinterpret_cast<const uint4*>(g_Qh);
    const uint4* X4p = reinterpret_cast<const uint4*>(g_xth);

    // ---- phase 1: per-edge dot xy (4 edges / iteration, uint4 loads) ----
#pragma unroll
    for (int i = 0; i < 4; ++i) {
        int ei = 4 * i + g;
        int er = s_r[w][ei], ec = s_c[w][ei];
        uint4 hr = hb4[er * 8 + l8];
        uint4 hc = hb4[ec * 8 + l8];
        float2 a0 = upk(hr.x), a1 = upk(hr.y), a2 = upk(hr.z), a3 = upk(hr.w);
        float2 b0 = upk(hc.x), b1 = upk(hc.y), b2 = upk(hc.z), b3 = upk(hc.w);
        float d = a0.x * b0.x + a0.y * b0.y + a1.x * b1.x + a1.y * b1.y
                + a2.x * b2.x + a2.y * b2.y + a3.x * b3.x + a3.y * b3.y;
        d += __shfl_xor_sync(FM, d, 4);
        d += __shfl_xor_sync(FM, d, 2);
        d += __shfl_xor_sync(FM, d, 1);
        if (l8 == 0) s_xy[w][ei] = d;
    }
    __syncwarp();

    // ---- phase 2: hyperbolic distance (lanes 0-15, one edge each) ----
    if (lane < 16) {
        float xyv = s_xy[w][lane];
        float al = 1.0f - 2.0f * xyv + sc_;
        float be = 1.0f - sr;
        float num2 = al * al * sr + be * be * sc_ - 2.0f * al * be * xyv;
        float den = fmaxf(1.0f - 2.0f * xyv + sr * sc_, EPSV);
        float nrm = __fdividef(sqrtf(fmaxf(num2, 0.0f)), den);
        s_dh[w][lane] = 2.0f * artanh_c(nrm);
    }
    __syncwarp();

    // ---- fused phases 3-5: hidden + z + score + scatter (4 edges / iter) ----
#pragma unroll
    for (int i = 0; i < 4; ++i) {
        int ei = 4 * i + g;
        int er = s_r[w][ei], ec = s_c[w][ei];
        float dh = s_dh[w][ei], di = s_dd[w][ei];
        float emi = s_em[w][ei];
        uint4 pu = P4p[er * 8 + l8];
        uint4 qu = Q4p[ec * 8 + l8];
        uint4 xu = X4p[ec * 8 + l8];       // prefetch scatter source
        float2 p0 = upk(pu.x), p1 = upk(pu.y), p2 = upk(pu.z), p3 = upk(pu.w);
        float2 q0 = upk(qu.x), q1 = upk(qu.y), q2 = upk(qu.z), q3 = upk(qu.w);
        float hv[8];
        hv[0] = p0.x + q0.x; hv[1] = p0.y + q0.y;
        hv[2] = p1.x + q1.x; hv[3] = p1.y + q1.y;
        hv[4] = p2.x + q2.x; hv[5] = p2.y + q2.y;
        hv[6] = p3.x + q3.x; hv[7] = p3.y + q3.y;
        float z = 0.f;
#pragma unroll
        for (int u = 0; u < 8; ++u) {
            float t = fmaf(di, wddv[u], fmaf(dh, wdv[u], hv[u]));
            z = fmaf(silu_fast(t), wa2v[u], z);
        }
        z += __shfl_xor_sync(FM, z, 4);
        z += __shfl_xor_sync(FM, z, 2);
        z += __shfl_xor_sync(FM, z, 1);
        float score = sigmoid_fast(z + b2s) * emi;   // em=0 on tail
        float2 x0 = upk(xu.x), x1 = upk(xu.y), x2 = upk(xu.z), x3 = upk(xu.w);
        float* dst = &g_agg[er * 64 + l8 * 8];
        red_add_v4(dst,     x0.x * score, x0.y * score, x1.x * score, x1.y * score);
        red_add_v4(dst + 4, x2.x * score, x2.y * score, x3.x * score, x3.y * score);
    }
}

// ===== K3 (2 thr/node, 2 nodes/thread): MLP + epilogue ======================
__global__ void __launch_bounds__(64)
k_node3(const float* __restrict__ Wm1,
        const float* __restrict__ bm1,
        const float* __restrict__ Wm2,
        const float* __restrict__ bm2,
        float* __restrict__ out, int n) {
    __shared__ float sW[64 * WS];
    __shared__ float sx[64 * XSTR];
    __shared__ __align__(16) float sb1[64];
    __shared__ __align__(16) float sb2[64];

    const int tid = threadIdx.x;
    const int slot = tid >> 1, p = tid & 1, p4 = 4 * p;
    const int base = blockIdx.x * 64;
    const int n0 = base + slot, n1 = base + slot + 32;
    const bool v0 = n0 < n, v1 = n1 < n;
    const int d0 = v0 ? n0 : 0, d1 = v1 ? n1 : 0;

    for (int idx = tid; idx < 4096; idx += 64) {
        int o = idx >> 6, k = idx & 63;
        sW[k * WS + o] = Wm1[idx];
    }
    sb1[tid] = bm1[tid];
    sb2[tid] = bm2[tid];
    __syncthreads();

    // stage agg/100 for both nodes
#pragma unroll
    for (int m = 0; m < 2; ++m) {
        int nd = m ? d1 : d0;
        int col = slot + m * 33;
        const float4* gag = reinterpret_cast<const float4*>(g_agg) + (size_t)nd * 16 + p * 8;
#pragma unroll
        for (int i = 0; i < 8; ++i) {
            float4 vv = gag[i];
            int kb = 32 * p + 4 * i;
            sx[(kb + 0) * XSTR + col] = vv.x * 0.01f;
            sx[(kb + 1) * XSTR + col] = vv.y * 0.01f;
            sx[(kb + 2) * XSTR + col] = vv.z * 0.01f;
            sx[(kb + 3) * XSTR + col] = vv.w * 0.01f;
        }
    }
    __syncwarp();

    // GEMV1 (dual)
    u64 acc0[16], acc1[16];
#pragma unroll
    for (int j = 0; j < 16; ++j) { acc0[j] = 0ull; acc1[j] = 0ull; }
    GEMVH2(acc0, acc1, sx, sW, slot, p4);

    // hid = silu_fast(acc + b1) staged back (interleaved outputs)
#pragma unroll
    for (int m = 0; m < 2; ++m) {
        int col = slot + m * 33;
        u64* am = m ? acc1 : acc0;
#pragma unroll
        for (int j = 0; j < 8; ++j) {
            float2 w0 = up64(am[2 * j]);
            float2 w1 = up64(am[2 * j + 1]);
            const float2* bp = reinterpret_cast<const float2*>(sb1 + 8 * j + p4);
            float2 b0 = bp[0], b1 = bp[1];
            int ob = 8 * j + p4;
            sx[(ob + 0) * XSTR + col] = silu_fast(w0.x + b0.x);
            sx[(ob + 1) * XSTR + col] = silu_fast(w0.y + b0.y);
            sx[(ob + 2) * XSTR + col] = silu_fast(w1.x + b1.x);
            sx[(ob + 3) * XSTR + col] = silu_fast(w1.y + b1.y);
        }
    }

    // restage Wm2
    __syncthreads();
    for (int idx = tid; idx < 4096; idx += 64) {
        int o = idx >> 6, k = idx & 63;
        sW[k * WS + o] = Wm2[idx];
    }
    __syncthreads();

    // GEMV2 (dual)
#pragma unroll
    for (int j = 0; j < 16; ++j) { acc0[j] = 0ull; acc1[j] = 0ull; }
    GEMVH2(acc0, acc1, sx, sW, slot, p4);

    // epilogue per node
#pragma unroll
    for (int m = 0; m < 2; ++m) {
        bool vm = m ? v1 : v0;
        int nd = m ? d1 : d0;
        u64* am = m ? acc1 : acc0;

        const float4* gxt = g_xt4 + (size_t)nd * 16;
        float ysq = 0.f;
#pragma unroll
        for (int j = 0; j < 8; ++j) {
            float4 xt = gxt[2 * j + p];
            float2 w0 = up64(am[2 * j]);
            float2 w1 = up64(am[2 * j + 1]);
            const float2* bp = reinterpret_cast<const float2*>(sb2 + 8 * j + p4);
            float2 b0 = bp[0], b1 = bp[1];
            float y0 = w0.x + b0.x + xt.x;
            float y1 = w0.y + b0.y + xt.y;
            float y2 = w1.x + b1.x + xt.z;
            float y3 = w1.y + b1.y + xt.w;
            ysq += y0 * y0 + y1 * y1 + y2 * y2 + y3 * y3;
            am[2 * j]     = pk64(y0, y1);
            am[2 * j + 1] = pk64(y2, y3);
        }
        ysq = psum(ysq);

        float ny = fmaxf(sqrtf(ysq), EPSV);
        float t = tanh_pos(ny);
        float s1 = t * __fdividef(1.0f, ny);
        float no = fmaxf(t, EPSV);                    // ||expmap0(y)|| = tanh(ny)
        float a2 = artanh_c(no) * __fdividef(1.0f, no);
        float sc = s1 * a2;

        float ssq = 0.f;
#pragma unroll
        for (int j = 0; j < 16; ++j) {
            float2 vv = up64(am[j]);
            float sx0 = siluf_(vv.x * sc);
            float sx1 = siluf_(vv.y * sc);
            ssq += sx0 * sx0 + sx1 * sx1;
            am[j] = pk64(sx0, sx1);
        }
        ssq = psum(ssq);
        float ns = fmaxf(sqrtf(ssq), EPSV);
        float s3 = tanh_pos(ns) * __fdividef(1.0f, ns);

        if (vm) {
            float4* op = reinterpret_cast<float4*>(out) + (size_t)nd * 16;
#pragma unroll
            for (int j = 0; j < 8; ++j) {
                float2 w0 = up64(am[2 * j]);
                float2 w1 = up64(am[2 * j + 1]);
                op[2 * j + p] = make_float4(w0.x * s3, w0.y * s3, w1.x * s3, w1.y * s3);
            }
        }
    }
}

// ------------------------------- launch -------------------------------------
extern "C" void kernel_launch(void* const* d_in, const int* in_sizes, int n_in,
                              void* d_out, int out_size) {
    const float* h         = (const float*)d_in[0];
    const float* distances = (const float*)d_in[1];
    const int*   edges     = (const int*)  d_in[2];
    // d_in[3] = node_mask (unused by reference)
    const float* edge_mask = (const float*)d_in[4];
    const float* W_lin     = (const float*)d_in[5];
    const float* b_lin     = (const float*)d_in[6];
    const float* Wa1       = (const float*)d_in[7];
    const float* ba1       = (const float*)d_in[8];
    const float* Wa2       = (const float*)d_in[9];
    const float* ba2       = (const float*)d_in[10];
    const float* Wm1       = (const float*)d_in[11];
    const float* bm1       = (const float*)d_in[12];
    const float* Wm2       = (const float*)d_in[13];
    const float* bm2       = (const float*)d_in[14];

    int N = in_sizes[0] / 64;
    int E = in_sizes[1];

    int blocksN = (N + 63) / 64;               // 64 nodes / 64-thread block
    int chunks = (E + 15) / 16;                // 16 edges per warp
    int blocksE = (chunks + 7) / 8;            // exact-fit: 1 chunk per warp

    k_nodeA<<<blocksN, 64>>>(h, W_lin, b_lin, Wa1, ba1, N);
    k_edge <<<blocksE, 256>>>(edges, distances, edge_mask, Wa1, Wa2, ba2, E);
    k_node3<<<blocksN, 64>>>(Wm1, bm1, Wm2, bm2, (float*)d_out, N);
}

// round 17
// speedup vs baseline: 1.0799x; 1.0366x over previous
#include <cuda_runtime.h>
#include <cuda_bf16.h>

#define EPSV 1e-7f
#define MAXN 50000
#define WS 68     // transposed weight row stride (floats), float4-aligned
#define XSTR 68   // x staging row stride (floats); node1 col offset +33

typedef unsigned long long u64;
struct __align__(16) U64x2 { u64 x, y; };

// ------------------------- static device scratch ---------------------------
__device__ __align__(16) float4 g_xt4[MAXN * 16];   // fp32 xtan
__device__ float g_nsq[MAXN];
__device__ __align__(16) float g_agg[MAXN * 64];    // fp32 accumulators
// bf16 tables for the edge kernel (4 dims per uint2)
__device__ __align__(16) uint2 g_hbh[MAXN * 16];
__device__ __align__(16) uint2 g_Ph [MAXN * 16];
__device__ __align__(16) uint2 g_Qh [MAXN * 16];
__device__ __align__(16) uint2 g_xth[MAXN * 16];

// ------------------------------ helpers ------------------------------------
__device__ __forceinline__ float artanh_c(float x) {
    x = fminf(x, 1.0f - EPSV);
    return 0.5f * __logf(__fdividef(1.0f + x, 1.0f - x));
}
__device__ __forceinline__ float tanh_pos(float x) {  // x >= 0
    float e = __expf(-2.0f * x);
    return (1.0f - e) * __fdividef(1.0f, 1.0f + e);
}
__device__ __forceinline__ float sigmoidf_(float z) {
    return __fdividef(1.0f, 1.0f + __expf(-z));
}
__device__ __forceinline__ float siluf_(float z) {   // exact (output path)
    return z * sigmoidf_(z);
}
__device__ __forceinline__ float tanh_fast(float x) {
    float r;
    asm("tanh.approx.f32 %0, %1;" : "=f"(r) : "f"(x));
    return r;
}
__device__ __forceinline__ float silu_fast(float x) {
    float t = tanh_fast(0.5f * x);
    return fmaf(0.5f * x, t, 0.5f * x);
}
__device__ __forceinline__ float sigmoid_fast(float z) {
    return fmaf(0.5f, tanh_fast(0.5f * z), 0.5f);
}
__device__ __forceinline__ void red_add_v4(float* a, float x, float y, float z, float w) {
    asm volatile("red.global.add.v4.f32 [%0], {%1, %2, %3, %4};"
                 :: "l"(a), "f"(x), "f"(y), "f"(z), "f"(w) : "memory");
}
__device__ __forceinline__ unsigned pk2(float a, float b) {
    __nv_bfloat162 t = __floats2bfloat162_rn(a, b);
    return *reinterpret_cast<unsigned*>(&t);
}
__device__ __forceinline__ float2 upk(unsigned u) {
    __nv_bfloat162 t = *reinterpret_cast<__nv_bfloat162*>(&u);
    return __bfloat1622float2(t);
}
__device__ __forceinline__ u64 pk64(float a, float b) {
    u64 r;
    asm("mov.b64 %0, {%1, %2};" : "=l"(r) : "f"(a), "f"(b));
    return r;
}
__device__ __forceinline__ float2 up64(u64 v) {
    float2 r;
    asm("mov.b64 {%0, %1}, %2;" : "=f"(r.x), "=f"(r.y) : "l"(v));
    return r;
}
__device__ __forceinline__ float psum(float v) {     // reduce over (2k,2k+1) pair
    return v + __shfl_xor_sync(0xffffffffu, v, 1);
}

// Vectorized transposed weight stage (stride-64 matrices, 16B-aligned rows):
// 64 threads, one row per thread, 16 LDG.128 + conflict-free scalar STS.
__device__ __forceinline__ void stage_w64(float* sW, const float* __restrict__ W,
                                          int tid) {
    const float4* src = reinterpret_cast<const float4*>(W + tid * 64);
#pragma unroll
    for (int j = 0; j < 16; ++j) {
        float4 v = src[j];
        sW[(4 * j + 0) * WS + tid] = v.x;
        sW[(4 * j + 1) * WS + tid] = v.y;
        sW[(4 * j + 2) * WS + tid] = v.z;
        sW[(4 * j + 3) * WS + tid] = v.w;
    }
}

// Stride-130 variant (Wa1 rows are only 8B-aligned): float2 loads.
__device__ __forceinline__ void stage_w130(float* sW, const float* __restrict__ W,
                                           int tid) {
    const float2* src = reinterpret_cast<const float2*>(W + tid * 130);
#pragma unroll
    for (int j = 0; j < 32; ++j) {
        float2 v = src[j];
        sW[(2 * j + 0) * WS + tid] = v.x;
        sW[(2 * j + 1) * WS + tid] = v.y;
    }
}

// Dual-node half-output GEMV: thread p computes outputs o=8j+4p+{0..3} for
// nodes in columns col0=slot and col1=slot+33. Weight LDS shared by both.
#define GEMVH2(a0, a1, sxp, swp, slot, p4)                                    \
    do {                                                                      \
        _Pragma("unroll 4")                                                   \
        for (int k = 0; k < 64; ++k) {                                        \
            float xk0 = (sxp)[k * XSTR + (slot)];                             \
            float xk1 = (sxp)[k * XSTR + (slot) + 33];                        \
            u64 x0_2, x1_2;                                                   \
            asm("mov.b64 %0, {%1, %1};" : "=l"(x0_2) : "f"(xk0));             \
            asm("mov.b64 %0, {%1, %1};" : "=l"(x1_2) : "f"(xk1));             \
            const float* wrow = (swp) + k * WS + (p4);                        \
            _Pragma("unroll")                                                 \
            for (int j = 0; j < 8; ++j) {                                     \
                U64x2 w2 = *reinterpret_cast<const U64x2*>(wrow + 8 * j);     \
                asm("fma.rn.f32x2 %0, %1, %2, %0;"                            \
                    : "+l"(a0[2 * j]) : "l"(w2.x), "l"(x0_2));                \
                asm("fma.rn.f32x2 %0, %1, %2, %0;"                            \
                    : "+l"(a0[2 * j + 1]) : "l"(w2.y), "l"(x0_2));            \
                asm("fma.rn.f32x2 %0, %1, %2, %0;"                            \
                    : "+l"(a1[2 * j]) : "l"(w2.x), "l"(x1_2));                \
                asm("fma.rn.f32x2 %0, %1, %2, %0;"                            \
                    : "+l"(a1[2 * j + 1]) : "l"(w2.y), "l"(x1_2));            \
            }                                                                 \
        }                                                                     \
    } while (0)

// hyperbolic chain for one node: consumes acc (xt halves), produces hb in acc,
// stages hb into sx column, writes node tables.
__device__ __forceinline__ void hyp_chain(
    u64* acc, const float* sb, int p4, float* sx, int col,
    int nd, bool valid, int p) {
    float xsq = 0.f, bsq = 0.f, rbp = 0.f;
#pragma unroll
    for (int j = 0; j < 8; ++j) {
        float2 v0 = up64(acc[2 * j]);
        float2 v1 = up64(acc[2 * j + 1]);
        const float2* bp = reinterpret_cast<const float2*>(sb + 8 * j + p4);
        float2 b0 = bp[0], b1 = bp[1];
        xsq += v0.x * v0.x + v0.y * v0.y + v1.x * v1.x + v1.y * v1.y;
        bsq += b0.x * b0.x + b0.y * b0.y + b1.x * b1.x + b1.y * b1.y;
        rbp += v0.x * b0.x + v0.y * b0.y + v1.x * b1.x + v1.y * b1.y;
    }
    xsq = psum(xsq); bsq = psum(bsq); rbp = psum(rbp);

    float nx = fmaxf(sqrtf(xsq), EPSV);
    float s0 = tanh_pos(nx) * __fdividef(1.0f, nx);
    float res2 = xsq * s0 * s0;
    float omr = 1.0f - res2;
    float rb = rbp * s0;

    float usq = bsq * omr * omr;
    float nu = fmaxf(sqrtf(usq), EPSV);
    float lam = 2.0f * __fdividef(1.0f, fmaxf(omr, EPSV));
    float ws = tanh_pos(0.5f * lam * nu) * __fdividef(1.0f, nu);
    float y2 = usq * ws * ws;
    float xy = ws * omr * rb;
    float ca = 1.0f + 2.0f * xy + y2;
    float den = fmaxf(1.0f + 2.0f * xy + res2 * y2, EPSV);
    float inv = __fdividef(1.0f, den);
    float c1 = ca * s0 * inv;
    float c2 = omr * omr * ws * inv;

    float hbsq = 0.f;
#pragma unroll
    for (int j = 0; j < 8; ++j) {
        float2 v0 = up64(acc[2 * j]);
        float2 v1 = up64(acc[2 * j + 1]);
        const float2* bp = reinterpret_cast<const float2*>(sb + 8 * j + p4);
        float2 b0 = bp[0], b1 = bp[1];
        float h0 = c1 * v0.x + c2 * b0.x;
        float h1 = c1 * v0.y + c2 * b0.y;
        float h2 = c1 * v1.x + c2 * b1.x;
        float h3 = c1 * v1.y + c2 * b1.y;
        hbsq += h0 * h0 + h1 * h1 + h2 * h2 + h3 * h3;
        acc[2 * j]     = pk64(h0, h1);
        acc[2 * j + 1] = pk64(h2, h3);
        int ob = 8 * j + p4;
        sx[(ob + 0) * XSTR + col] = h0;
        sx[(ob + 1) * XSTR + col] = h1;
        sx[(ob + 2) * XSTR + col] = h2;
        sx[(ob + 3) * XSTR + col] = h3;
    }
    hbsq = psum(hbsq);
    float nbn = fmaxf(sqrtf(hbsq), EPSV);
    float at = artanh_c(nbn) * __fdividef(1.0f, nbn);

    if (valid) {
        if (p == 0) g_nsq[nd] = hbsq;
        uint2*  gbh = g_hbh + (size_t)nd * 16;
        uint2*  gth = g_xth + (size_t)nd * 16;
        float4* gxt = g_xt4 + (size_t)nd * 16;
        float4* gag = reinterpret_cast<float4*>(g_agg) + (size_t)nd * 16;
#pragma unroll
        for (int j = 0; j < 8; ++j) {
            int u = 2 * j + p;
            float2 v0 = up64(acc[2 * j]);
            float2 v1 = up64(acc[2 * j + 1]);
            gbh[u] = make_uint2(pk2(v0.x, v0.y), pk2(v1.x, v1.y));
            float4 xt = make_float4(v0.x * at, v0.y * at, v1.x * at, v1.y * at);
            gxt[u] = xt;
            gth[u] = make_uint2(pk2(xt.x, xt.y), pk2(xt.z, xt.w));
            gag[u] = make_float4(0.f, 0.f, 0.f, 0.f);
        }
    }
}

// ======= K1 (2 thr/node, 2 nodes/thread, 64 nodes/block of 64 thr) ==========
__global__ void __launch_bounds__(64)
k_nodeA(const float* __restrict__ h,
        const float* __restrict__ Wlin,
        const float* __restrict__ blin,
        const float* __restrict__ Wa1,
        const float* __restrict__ ba1, int n) {
    __shared__ float sW[64 * WS];
    __shared__ float sx[64 * XSTR];
    __shared__ __align__(16) float sb[64];

    const int tid = threadIdx.x;
    const int slot = tid >> 1, p = tid & 1, p4 = 4 * p;
    const int base = blockIdx.x * 64;
    const int n0 = base + slot, n1 = base + slot + 32;
    const bool v0 = n0 < n, v1 = n1 < n;
    const int d0 = v0 ? n0 : 0, d1 = v1 ? n1 : 0;

    // stage Wlin^T + blin (vectorized: one row per thread)
    stage_w64(sW, Wlin, tid);
    sb[tid] = blin[tid];
    __syncthreads();

    // stage lm for both nodes
#pragma unroll
    for (int m = 0; m < 2; ++m) {
        int nd = m ? d1 : d0;
        int col = slot + m * 33;
        const float4* hp = reinterpret_cast<const float4*>(h) + (size_t)nd * 16 + p * 8;
        float4 hv[8];
        float hsq = 0.f;
#pragma unroll
        for (int i = 0; i < 8; ++i) {
            hv[i] = hp[i];
            hsq += hv[i].x * hv[i].x + hv[i].y * hv[i].y + hv[i].z * hv[i].z + hv[i].w * hv[i].w;
        }
        hsq = psum(hsq);
        float nh = fmaxf(sqrtf(hsq), EPSV);
        float a = artanh_c(nh) * __fdividef(1.0f, nh);
#pragma unroll
        for (int i = 0; i < 8; ++i) {
            int kb = 32 * p + 4 * i;
            sx[(kb + 0) * XSTR + col] = hv[i].x * a;
            sx[(kb + 1) * XSTR + col] = hv[i].y * a;
            sx[(kb + 2) * XSTR + col] = hv[i].z * a;
            sx[(kb + 3) * XSTR + col] = hv[i].w * a;
        }
    }
    __syncwarp();

    // GEMV1 (dual): xt for both nodes
    u64 acc0[16], acc1[16];
#pragma unroll
    for (int j = 0; j < 16; ++j) { acc0[j] = 0ull; acc1[j] = 0ull; }
    GEMVH2(acc0, acc1, sx, sW, slot, p4);

    // hyperbolic chain + table writes + hb restage (per node)
    hyp_chain(acc0, sb, p4, sx, slot,      d0, v0, p);
    hyp_chain(acc1, sb, p4, sx, slot + 33, d1, v1, p);

    // restage Wa1[:,0:64]^T + ba1 ; GEMV P (dual)
    __syncthreads();
    stage_w130(sW, Wa1, tid);
    sb[tid] = ba1[tid];
    __syncthreads();

#pragma unroll
    for (int j = 0; j < 16; ++j) { acc0[j] = 0ull; acc1[j] = 0ull; }
    GEMVH2(acc0, acc1, sx, sW, slot, p4);
#pragma unroll
    for (int m = 0; m < 2; ++m) {
        bool vm = m ? v1 : v0;
        if (!vm) continue;
        int nd = m ? d1 : d0;
        u64* am = m ? acc1 : acc0;
        uint2* gp = g_Ph + (size_t)nd * 16;
#pragma unroll
        for (int j = 0; j < 8; ++j) {
            float2 w0 = up64(am[2 * j]);
            float2 w1 = up64(am[2 * j + 1]);
            const float2* bp = reinterpret_cast<const float2*>(sb + 8 * j + p4);
            float2 b0 = bp[0], b1 = bp[1];
            gp[2 * j + p] = make_uint2(pk2(w0.x + b0.x, w0.y + b0.y),
                                       pk2(w1.x + b1.x, w1.y + b1.y));
        }
    }

    // restage Wa1[:,64:128]^T ; GEMV Q (dual)
    __syncthreads();
    stage_w130(sW, Wa1 + 64, tid);
    __syncthreads();

#pragma unroll
    for (int j = 0; j < 16; ++j) { acc0[j] = 0ull; acc1[j] = 0ull; }
    GEMVH2(acc0, acc1, sx, sW, slot, p4);
#pragma unroll
    for (int m = 0; m < 2; ++m) {
        bool vm = m ? v1 : v0;
        if (!vm) continue;
        int nd = m ? d1 : d0;
        u64* am = m ? acc1 : acc0;
        uint2* gq = g_Qh + (size_t)nd * 16;
#pragma unroll
        for (int j = 0; j < 8; ++j) {
            float2 w0 = up64(am[2 * j]);
            float2 w1 = up64(am[2 * j + 1]);
            gq[2 * j + p] = make_uint2(pk2(w0.x, w0.y), pk2(w1.x, w1.y));
        }
    }
}

// ===== K2: edge attention + scatter (8 lanes/edge, 4 edges/iter, uint4) =====
__global__ void __launch_bounds__(256)
k_edge(const int* __restrict__ edges,
       const float* __restrict__ dist,
       const float* __restrict__ emask,
       const float* __restrict__ Wa1,
       const float* __restrict__ Wa2,
       const float* __restrict__ ba2, int E) {
    __shared__ int   s_r [8][32];
    __shared__ int   s_c [8][32];
    __shared__ float s_xy[8][32];
    __shared__ float s_dh[8][32];
    __shared__ float s_dd[8][32];
    __shared__ float s_em[8][32];

    const int lane = threadIdx.x & 31, w = threadIdx.x >> 5;
    const int g = lane >> 3, l8 = lane & 7;       // 4 edge-groups of 8 lanes
    const unsigned FM = 0xffffffffu;

    // per-lane weights for hidden dims [8*l8, 8*l8+8)
    float wdv[8], wddv[8], wa2v[8];
#pragma unroll
    for (int u = 0; u < 8; ++u) {
        wdv[u]  = Wa1[(8 * l8 + u) * 130 + 128];
        wddv[u] = Wa1[(8 * l8 + u) * 130 + 129];
        wa2v[u] = Wa2[8 * l8 + u];
    }
    float b2s = ba2[0];

    const int chunks = (E + 31) >> 5;
    const int ch = blockIdx.x * 8 + w;            // exact-fit: one chunk per warp
    if (ch >= chunks) return;

    int e = ch * 32 + lane;
    bool v = e < E;
    int r = 0, c = 0;
    float dd = 0.f, em = 0.f, sr = 0.f, sc_ = 0.f;
    if (v) {
        r = edges[e];
        c = edges[E + e];
        dd = dist[e];
        em = emask[e];
        sr = g_nsq[r];
        sc_ = g_nsq[c];
    }
    s_r[w][lane] = r; s_c[w][lane] = c;
    s_dd[w][lane] = dd; s_em[w][lane] = em;
    __syncwarp();

    const uint4* hb4 = reinterpret_cast<const uint4*>(g_hbh);
    const uint4* P4p = reinterpret_cast<const uint4*>(g_Ph);
    const uint4* Q4p = reinterpret_cast<const uint4*>(g_Qh);
    const uint4* X4p = reinterpret_cast<const uint4*>(g_xth);

    // ---- phase 1: per-edge dot xy (4 edges / iteration, uint4 loads) ----
#pragma unroll
    for (int i = 0; i < 8; ++i) {
        int ei = 4 * i + g;
        int er = s_r[w][ei], ec = s_c[w][ei];
        uint4 hr = hb4[er * 8 + l8];
        uint4 hc = hb4[ec * 8 + l8];
        float2 a0 = upk(hr.x), a1 = upk(hr.y), a2 = upk(hr.z), a3 = upk(hr.w);
        float2 b0 = upk(hc.x), b1 = upk(hc.y), b2 = upk(hc.z), b3 = upk(hc.w);
        float d = a0.x * b0.x + a0.y * b0.y + a1.x * b1.x + a1.y * b1.y
                + a2.x * b2.x + a2.y * b2.y + a3.x * b3.x + a3.y * b3.y;
        d += __shfl_xor_sync(FM, d, 4);
        d += __shfl_xor_sync(FM, d, 2);
        d += __shfl_xor_sync(FM, d, 1);
        if (l8 == 0) s_xy[w][ei] = d;
    }
    __syncwarp();

    // ---- phase 2: hyperbolic distance (lane = edge) ----
    {
        float xyv = s_xy[w][lane];
        float al = 1.0f - 2.0f * xyv + sc_;
        float be = 1.0f - sr;
        float num2 = al * al * sr + be * be * sc_ - 2.0f * al * be * xyv;
        float den = fmaxf(1.0f - 2.0f * xyv + sr * sc_, EPSV);
        float nrm = __fdividef(sqrtf(fmaxf(num2, 0.0f)), den);
        s_dh[w][lane] = 2.0f * artanh_c(nrm);
    }
    __syncwarp();

    // ---- fused phases 3-5: hidden + z + score + scatter (4 edges / iter) ----
#pragma unroll
    for (int i = 0; i < 8; ++i) {
        int ei = 4 * i + g;
        int er = s_r[w][ei], ec = s_c[w][ei];
        float dh = s_dh[w][ei], di = s_dd[w][ei];
        float emi = s_em[w][ei];
        uint4 pu = P4p[er * 8 + l8];
        uint4 qu = Q4p[ec * 8 + l8];
        uint4 xu = X4p[ec * 8 + l8];       // prefetch scatter source
        float2 p0 = upk(pu.x), p1 = upk(pu.y), p2 = upk(pu.z), p3 = upk(pu.w);
        float2 q0 = upk(qu.x), q1 = upk(qu.y), q2 = upk(qu.z), q3 = upk(qu.w);
        float hv[8];
        hv[0] = p0.x + q0.x; hv[1] = p0.y + q0.y;
        hv[2] = p1.x + q1.x; hv[3] = p1.y + q1.y;
        hv[4] = p2.x + q2.x; hv[5] = p2.y + q2.y;
        hv[6] = p3.x + q3.x; hv[7] = p3.y + q3.y;
        float z = 0.f;
#pragma unroll
        for (int u = 0; u < 8; ++u) {
            float t = fmaf(di, wddv[u], fmaf(dh, wdv[u], hv[u]));
            z = fmaf(silu_fast(t), wa2v[u], z);
        }
        z += __shfl_xor_sync(FM, z, 4);
        z += __shfl_xor_sync(FM, z, 2);
        z += __shfl_xor_sync(FM, z, 1);
        float score = sigmoid_fast(z + b2s) * emi;   // em=0 on tail
        float2 x0 = upk(xu.x), x1 = upk(xu.y), x2 = upk(xu.z), x3 = upk(xu.w);
        float* dst = &g_agg[er * 64 + l8 * 8];
        red_add_v4(dst,     x0.x * score, x0.y * score, x1.x * score, x1.y * score);
        red_add_v4(dst + 4, x2.x * score, x2.y * score, x3.x * score, x3.y * score);
    }
}

// ===== K3 (2 thr/node, 2 nodes/thread): MLP + epilogue ======================
__global__ void __launch_bounds__(64)
k_node3(const float* __restrict__ Wm1,
        const float* __restrict__ bm1,
        const float* __restrict__ Wm2,
        const float* __restrict__ bm2,
        float* __restrict__ out, int n) {
    __shared__ float sW[64 * WS];
    __shared__ float sx[64 * XSTR];
    __shared__ __align__(16) float sb1[64];
    __shared__ __align__(16) float sb2[64];

    const int tid = threadIdx.x;
    const int slot = tid >> 1, p = tid & 1, p4 = 4 * p;
    const int base = blockIdx.x * 64;
    const int n0 = base + slot, n1 = base + slot + 32;
    const bool v0 = n0 < n, v1 = n1 < n;
    const int d0 = v0 ? n0 : 0, d1 = v1 ? n1 : 0;

    stage_w64(sW, Wm1, tid);
    sb1[tid] = bm1[tid];
    sb2[tid] = bm2[tid];
    __syncthreads();

    // stage agg/100 for both nodes
#pragma unroll
    for (int m = 0; m < 2; ++m) {
        int nd = m ? d1 : d0;
        int col = slot + m * 33;
        const float4* gag = reinterpret_cast<const float4*>(g_agg) + (size_t)nd * 16 + p * 8;
#pragma unroll
        for (int i = 0; i < 8; ++i) {
            float4 vv = gag[i];
            int kb = 32 * p + 4 * i;
            sx[(kb + 0) * XSTR + col] = vv.x * 0.01f;
            sx[(kb + 1) * XSTR + col] = vv.y * 0.01f;
            sx[(kb + 2) * XSTR + col] = vv.z * 0.01f;
            sx[(kb + 3) * XSTR + col] = vv.w * 0.01f;
        }
    }
    __syncwarp();

    // GEMV1 (dual)
    u64 acc0[16], acc1[16];
#pragma unroll
    for (int j = 0; j < 16; ++j) { acc0[j] = 0ull; acc1[j] = 0ull; }
    GEMVH2(acc0, acc1, sx, sW, slot, p4);

    // hid = silu_fast(acc + b1) staged back (interleaved outputs)
#pragma unroll
    for (int m = 0; m < 2; ++m) {
        int col = slot + m * 33;
        u64* am = m ? acc1 : acc0;
#pragma unroll
        for (int j = 0; j < 8; ++j) {
            float2 w0 = up64(am[2 * j]);
            float2 w1 = up64(am[2 * j + 1]);
            const float2* bp = reinterpret_cast<const float2*>(sb1 + 8 * j + p4);
            float2 b0 = bp[0], b1 = bp[1];
            int ob = 8 * j + p4;
            sx[(ob + 0) * XSTR + col] = silu_fast(w0.x + b0.x);
            sx[(ob + 1) * XSTR + col] = silu_fast(w0.y + b0.y);
            sx[(ob + 2) * XSTR + col] = silu_fast(w1.x + b1.x);
            sx[(ob + 3) * XSTR + col] = silu_fast(w1.y + b1.y);
        }
    }

    // restage Wm2
    __syncthreads();
    stage_w64(sW, Wm2, tid);
    __syncthreads();

    // GEMV2 (dual)
#pragma unroll
    for (int j = 0; j < 16; ++j) { acc0[j] = 0ull; acc1[j] = 0ull; }
    GEMVH2(acc0, acc1, sx, sW, slot, p4);

    // epilogue per node
#pragma unroll
    for (int m = 0; m < 2; ++m) {
        bool vm = m ? v1 : v0;
        int nd = m ? d1 : d0;
        u64* am = m ? acc1 : acc0;

        const float4* gxt = g_xt4 + (size_t)nd * 16;
        float ysq = 0.f;
#pragma unroll
        for (int j = 0; j < 8; ++j) {
            float4 xt = gxt[2 * j + p];
            float2 w0 = up64(am[2 * j]);
            float2 w1 = up64(am[2 * j + 1]);
            const float2* bp = reinterpret_cast<const float2*>(sb2 + 8 * j + p4);
            float2 b0 = bp[0], b1 = bp[1];
            float y0 = w0.x + b0.x + xt.x;
            float y1 = w0.y + b0.y + xt.y;
            float y2 = w1.x + b1.x + xt.z;
            float y3 = w1.y + b1.y + xt.w;
            ysq += y0 * y0 + y1 * y1 + y2 * y2 + y3 * y3;
            am[2 * j]     = pk64(y0, y1);
            am[2 * j + 1] = pk64(y2, y3);
        }
        ysq = psum(ysq);

        float ny = fmaxf(sqrtf(ysq), EPSV);
        float t = tanh_pos(ny);
        float s1 = t * __fdividef(1.0f, ny);
        float no = fmaxf(t, EPSV);                    // ||expmap0(y)|| = tanh(ny)
        float a2 = artanh_c(no) * __fdividef(1.0f, no);
        float sc = s1 * a2;

        float ssq = 0.f;
#pragma unroll
        for (int j = 0; j < 16; ++j) {
            float2 vv = up64(am[j]);
            float sx0 = siluf_(vv.x * sc);
            float sx1 = siluf_(vv.y * sc);
            ssq += sx0 * sx0 + sx1 * sx1;
            am[j] = pk64(sx0, sx1);
        }
        ssq = psum(ssq);
        float ns = fmaxf(sqrtf(ssq), EPSV);
        float s3 = tanh_pos(ns) * __fdividef(1.0f, ns);

        if (vm) {
            float4* op = reinterpret_cast<float4*>(out) + (size_t)nd * 16;
#pragma unroll
            for (int j = 0; j < 8; ++j) {
                float2 w0 = up64(am[2 * j]);
                float2 w1 = up64(am[2 * j + 1]);
                op[2 * j + p] = make_float4(w0.x * s3, w0.y * s3, w1.x * s3, w1.y * s3);
            }
        }
    }
}

// ------------------------------- launch -------------------------------------
extern "C" void kernel_launch(void* const* d_in, const int* in_sizes, int n_in,
                              void* d_out, int out_size) {
    const float* h         = (const float*)d_in[0];
    const float* distances = (const float*)d_in[1];
    const int*   edges     = (const int*)  d_in[2];
    // d_in[3] = node_mask (unused by reference)
    const float* edge_mask = (const float*)d_in[4];
    const float* W_lin     = (const float*)d_in[5];
    const float* b_lin     = (const float*)d_in[6];
    const float* Wa1       = (const float*)d_in[7];
    const float* ba1       = (const float*)d_in[8];
    const float* Wa2       = (const float*)d_in[9];
    const float* ba2       = (const float*)d_in[10];
    const float* Wm1       = (const float*)d_in[11];
    const float* bm1       = (const float*)d_in[12];
    const float* Wm2       = (const float*)d_in[13];
    const float* bm2       = (const float*)d_in[14];

    int N = in_sizes[0] / 64;
    int E = in_sizes[1];

    int blocksN = (N + 63) / 64;               // 64 nodes / 64-thread block
    int chunks = (E + 31) / 32;
    int blocksE = (chunks + 7) / 8;            // exact-fit: 1 chunk per warp

    k_nodeA<<<blocksN, 64>>>(h, W_lin, b_lin, Wa1, ba1, N);
    k_edge <<<blocksE, 256>>>(edges, distances, edge_mask, Wa1, Wa2, ba2, E);
    k_node3<<<blocksN, 64>>>(Wm1, bm1, Wm2, bm2, (float*)d_out, N);
}